// round 4
// baseline (speedup 1.0000x reference)
#include <cuda_runtime.h>
#include <math.h>
#include <stdint.h>

// ---------------------------------------------------------------------------
// FPLSTM layer: S=512, B=128, I=H=1024
//   pre = X @ Wx^T + bx                         (one big GEMM, cp.async 3-stage)
//   per step t (persistent kernel, 128 CTAs, weights SMEM-resident):
//     gates = sigmoid(pre[t,:,:4H] + h @ Wh^T + bh)   (i,o,z,f)
//     m = z * tanh(c)
//     u = tanh(pre[t,:,4H:] + m @ Wum^T + bum)
//     c = i*u + f*c ;  h = o*tanh(c)
// All GEMM operands pre-rounded to tf32 (RNA) in global memory so staging is
// raw cp.async / LDG with zero conversions in the hot loops.
// ---------------------------------------------------------------------------

namespace {
constexpr int SEQ  = 512;
constexpr int NB   = 128;
constexpr int K    = 1024;
constexpr int H    = 1024;
constexpr int NPRE = 5 * H;   // 5120

constexpr int NCTA  = 128;
constexpr int UCOLS = H / NCTA;       // 8 owned h-columns per CTA
constexpr int LDW   = K + 4;          // padded weight stride (words)
constexpr int BK    = 32;
constexpr int LDA   = BK + 4;         // 36 words (row=144B, 16B aligned)
constexpr int ABUF  = NB * LDA;       // 4608 words per A stage
// lstm dynamic smem layout (u32 words)
constexpr int OFF_W   = 0;                        // 40 rows x LDW
constexpr int OFF_AS  = 40 * LDW;                 // 41120
constexpr int OFF_IOF = OFF_AS + 2 * ABUF;        // 50336 : [3][128][8]
constexpr int OFF_C   = OFF_IOF + 3 * NB * UCOLS; // 53408 : [128][8]
constexpr int SMEM_WORDS = OFF_C + NB * UCOLS;    // 54432 -> 217728 bytes

// pre_kernel smem: 3 stages of (128 A rows + 128 B rows) x LDA
constexpr int P_STAGE = 256 * LDA;                // 9216 words
constexpr int P_SMEM  = 3 * P_STAGE;              // 27648 words -> 110592 bytes

constexpr size_t X4 = (size_t)SEQ * NB * K / 4;   // 16777216 float4
constexpr size_t W4 = (size_t)NPRE * K / 4;       // 1310720 float4
}

// Scratch (allocation-free __device__ globals)
__device__ __align__(16) float g_pre[(size_t)SEQ * NB * NPRE];
__device__ __align__(16) float g_xr[(size_t)SEQ * NB * K];   // tf32-rounded X
__device__ __align__(16) float g_wxr[(size_t)NPRE * K];      // tf32-rounded Wx
__device__ __align__(16) float g_hr[NB * H];                 // tf32-rounded h
__device__ __align__(16) float g_m[NB * H];                  // tf32-rounded m
__device__ unsigned g_bar;

__device__ __forceinline__ uint32_t f2tf(float f) {
    uint32_t u;
    asm("cvt.rna.tf32.f32 %0, %1;" : "=r"(u) : "f"(f));
    return u;
}
__device__ __forceinline__ float f2tf_f(float f) { return __uint_as_float(f2tf(f)); }

__device__ __forceinline__ void mma_tf32(float* c, const uint32_t* a, const uint32_t* b) {
    asm volatile(
        "mma.sync.aligned.m16n8k8.row.col.f32.tf32.tf32.f32 "
        "{%0,%1,%2,%3}, {%4,%5,%6,%7}, {%8,%9}, {%0,%1,%2,%3};\n"
        : "+f"(c[0]), "+f"(c[1]), "+f"(c[2]), "+f"(c[3])
        : "r"(a[0]), "r"(a[1]), "r"(a[2]), "r"(a[3]),
          "r"(b[0]), "r"(b[1]));
}

__device__ __forceinline__ float fast_sigmoid(float x) {
    return __fdividef(1.0f, 1.0f + __expf(-x));
}
__device__ __forceinline__ float fast_tanh(float x) {
    return 1.0f - __fdividef(2.0f, __expf(2.0f * x) + 1.0f);
}

__device__ __forceinline__ void cp16(uint32_t smem_byte_addr, const void* gptr) {
    asm volatile("cp.async.cg.shared.global [%0], [%1], 16;\n"
                 :: "r"(smem_byte_addr), "l"(gptr));
}
__device__ __forceinline__ void cp_commit() {
    asm volatile("cp.async.commit_group;\n");
}
template <int N>
__device__ __forceinline__ void cp_wait() {
    asm volatile("cp.async.wait_group %0;\n" :: "n"(N));
}

// ---------------------------------------------------------------------------
// round_kernel: tf32-round X and Wx into scratch; reset grid barrier
// ---------------------------------------------------------------------------
__global__ __launch_bounds__(256) void round_kernel(const float4* __restrict__ X,
                                                    const float4* __restrict__ Wx) {
    const size_t i = (size_t)blockIdx.x * 256 + threadIdx.x;
    if (i == 0) g_bar = 0u;
    if (i < X4) {
        const float4 v = X[i];
        float4 r = make_float4(f2tf_f(v.x), f2tf_f(v.y), f2tf_f(v.z), f2tf_f(v.w));
        reinterpret_cast<float4*>(g_xr)[i] = r;
    } else if (i < X4 + W4) {
        const size_t j = i - X4;
        const float4 v = Wx[j];
        float4 r = make_float4(f2tf_f(v.x), f2tf_f(v.y), f2tf_f(v.z), f2tf_f(v.w));
        reinterpret_cast<float4*>(g_wxr)[j] = r;
    }
}

// ---------------------------------------------------------------------------
// pre_kernel: pre = Xr @ Wxr^T + bx   (M=65536, N=5120, K=1024)
// BM=128, BN=128, BK=32, 256 threads, 3-stage cp.async pipeline.
// ---------------------------------------------------------------------------
__device__ __forceinline__ void pre_issue(uint32_t smbase, int stage,
                                          const float* __restrict__ Asrc,
                                          const float* __restrict__ Bsrc,
                                          int kt, int tid) {
    const uint32_t sb = smbase + (uint32_t)(stage * P_STAGE) * 4u;
    #pragma unroll
    for (int j = 0; j < 8; ++j) {
        const int i  = tid + j * 256;
        const int r  = i >> 3;
        const int ch = i & 7;
        const float* src = (r < 128)
            ? Asrc + (size_t)r * K + kt + ch * 4
            : Bsrc + (size_t)(r - 128) * K + kt + ch * 4;
        cp16(sb + (uint32_t)(r * LDA + ch * 4) * 4u, src);
    }
    cp_commit();
}

__global__ __launch_bounds__(256, 1) void pre_kernel(const float* __restrict__ bx) {
    extern __shared__ uint32_t sm_u[];
    const uint32_t smbase = (uint32_t)__cvta_generic_to_shared(sm_u);

    const int tid  = threadIdx.x;
    const int lane = tid & 31;
    const int warp = tid >> 5;
    const int wm = warp >> 2;        // 0..1  (64 rows each)
    const int wn = warp & 3;         // 0..3  (32 cols each)
    const int ar = lane >> 2;
    const int aq = lane & 3;

    const float* Asrc = g_xr  + (size_t)blockIdx.y * 128 * K;
    const float* Bsrc = g_wxr + (size_t)blockIdx.x * 128 * K;

    float acc[4][4][4] = {};

    pre_issue(smbase, 0, Asrc, Bsrc, 0, tid);
    pre_issue(smbase, 1, Asrc, Bsrc, BK, tid);

    #pragma unroll 1
    for (int kt = 0; kt < K / BK; ++kt) {
        if (kt < K / BK - 2) { cp_wait<1>(); } else { cp_wait<0>(); }
        __syncthreads();
        if (kt + 2 < K / BK)
            pre_issue(smbase, (kt + 2) % 3, Asrc, Bsrc, (kt + 2) * BK, tid);

        const uint32_t* buf = sm_u + (kt % 3) * P_STAGE;
        #pragma unroll
        for (int k8 = 0; k8 < BK / 8; ++k8) {
            const int ac = k8 * 8 + aq;
            uint32_t af[4][4], bf[4][2];
            #pragma unroll
            for (int tm = 0; tm < 4; ++tm) {
                const uint32_t* p = buf + (wm * 64 + tm * 16 + ar) * LDA + ac;
                af[tm][0] = p[0];
                af[tm][1] = p[8 * LDA];
                af[tm][2] = p[4];
                af[tm][3] = p[8 * LDA + 4];
            }
            #pragma unroll
            for (int tn = 0; tn < 4; ++tn) {
                const uint32_t* q = buf + (128 + wn * 32 + tn * 8 + ar) * LDA + ac;
                bf[tn][0] = q[0];
                bf[tn][1] = q[4];
            }
            #pragma unroll
            for (int tm = 0; tm < 4; ++tm)
                #pragma unroll
                for (int tn = 0; tn < 4; ++tn)
                    mma_tf32(&acc[tm][tn][0], af[tm], bf[tn]);
        }
        __syncthreads();
    }

    #pragma unroll
    for (int tm = 0; tm < 4; ++tm) {
        #pragma unroll
        for (int tn = 0; tn < 4; ++tn) {
            const int r0 = wm * 64 + tm * 16 + ar;
            const int c0 = wn * 32 + tn * 8 + aq * 2;
            #pragma unroll
            for (int j = 0; j < 4; ++j) {
                const int rr = r0 + (j >> 1) * 8;
                const int cc = c0 + (j & 1);
                const int gm = blockIdx.y * 128 + rr;
                const int gn = blockIdx.x * 128 + cc;
                g_pre[(size_t)gm * NPRE + gn] = acc[tm][tn][j] + __ldg(bx + gn);
            }
        }
    }
}

// ---------------------------------------------------------------------------
// Persistent recurrence kernel
// ---------------------------------------------------------------------------
__device__ __forceinline__ void grid_barrier(unsigned target) {
    __syncthreads();
    if (threadIdx.x == 0) {
        asm volatile("red.release.gpu.global.add.u32 [%0], %1;\n"
                     :: "l"(&g_bar), "r"(1u) : "memory");
        unsigned v;
        do {
            asm volatile("ld.acquire.gpu.global.u32 %0, [%1];\n"
                         : "=r"(v) : "l"(&g_bar) : "memory");
        } while (v < target);
    }
    __syncthreads();
}

// copy one 128 x BK A-tile from global (tf32-rounded) into smem stage
__device__ __forceinline__ void lstm_issueA(uint32_t smbase, int stage,
                                            const float* __restrict__ src,
                                            int kt, int tid) {
    const uint32_t sb = smbase + (uint32_t)((OFF_AS + stage * ABUF)) * 4u;
    #pragma unroll
    for (int j = 0; j < 4; ++j) {
        const int i  = tid + j * 256;
        const int r  = i >> 3;
        const int ch = i & 7;
        cp16(sb + (uint32_t)(r * LDA + ch * 4) * 4u,
             src + (size_t)r * H + kt + ch * 4);
    }
    cp_commit();
}

__global__ __launch_bounds__(256, 1) void lstm_kernel(const float* __restrict__ Wh,
                                                      const float* __restrict__ bh,
                                                      const float* __restrict__ Wum,
                                                      const float* __restrict__ bum,
                                                      float* __restrict__ out) {
    extern __shared__ uint32_t sm_u[];
    const uint32_t smbase = (uint32_t)__cvta_generic_to_shared(sm_u);
    uint32_t* W_s   = sm_u + OFF_W;      // rows 0..31: Wh slices; 32..39: Wum slice
    float*    iof_s = reinterpret_cast<float*>(sm_u + OFF_IOF);  // [3][128][8]
    float*    c_s   = reinterpret_cast<float*>(sm_u + OFF_C);    // [128][8]

    const int tid   = threadIdx.x;
    const int lane  = tid & 31;
    const int warp  = tid >> 5;
    const int uBase = blockIdx.x * UCOLS;

    // ---- preload weight slices (fp32 -> tf32, once) ----
    for (int i = tid; i < 40 * 256; i += 256) {
        const int row = i >> 8;
        const int c4  = (i & 255) * 4;
        const float* src;
        if (row < 32) {
            const int g = row >> 3, r = row & 7;
            src = Wh + (size_t)(g * H + uBase + r) * K;
        } else {
            src = Wum + (size_t)(uBase + (row - 32)) * K;
        }
        const float4 v = *reinterpret_cast<const float4*>(src + c4);
        uint4 d = make_uint4(f2tf(v.x), f2tf(v.y), f2tf(v.z), f2tf(v.w));
        *reinterpret_cast<uint4*>(W_s + row * LDW + c4) = d;
    }
    for (int i = tid; i < NB * UCOLS; i += 256) c_s[i] = 0.0f;
    __syncthreads();

    // phase-1 warp layout: wm in [0,4) -> 32 batch rows; wn in [0,2) -> 16 gate cols
    const int wm = warp >> 1;
    const int wn = warp & 1;
    const int ar = lane >> 2;
    const int aq = lane & 3;

    float bhreg[2][2];
    #pragma unroll
    for (int tn = 0; tn < 2; ++tn)
        #pragma unroll
        for (int jb = 0; jb < 2; ++jb) {
            const int gi = wn * 16 + tn * 8 + aq * 2 + jb;
            bhreg[tn][jb] = bh[(gi >> 3) * H + uBase + (gi & 7)];
        }
    const float2 bureg = *reinterpret_cast<const float2*>(bum + uBase + aq * 2);

    unsigned bar_target = NCTA;

    for (int t = 0; t < SEQ; ++t) {
        const float* pre_t = g_pre + (size_t)t * NB * NPRE;

        // ================= Phase 1: gates =================
        {
            // prefetch pre slices for the epilogue
            float2 pre2[2][2][2];   // [tm][jh][tn]
            #pragma unroll
            for (int tm = 0; tm < 2; ++tm)
                #pragma unroll
                for (int jh = 0; jh < 2; ++jh)
                    #pragma unroll
                    for (int tn = 0; tn < 2; ++tn) {
                        const int b = wm * 32 + tm * 16 + ar + 8 * jh;
                        const int g = wn * 2 + tn;
                        pre2[tm][jh][tn] = __ldcg(reinterpret_cast<const float2*>(
                            pre_t + (size_t)b * NPRE + g * H + uBase + aq * 2));
                    }

            float acc[2][2][4] = {};
            if (t > 0) {
                lstm_issueA(smbase, 0, g_hr, 0, tid);
                #pragma unroll 1
                for (int kt = 0; kt < K / BK; ++kt) {
                    cp_wait<0>();
                    __syncthreads();
                    if (kt + 1 < K / BK)
                        lstm_issueA(smbase, (kt + 1) & 1, g_hr, (kt + 1) * BK, tid);

                    const uint32_t* cur = sm_u + OFF_AS + (kt & 1) * ABUF;
                    #pragma unroll
                    for (int k8 = 0; k8 < BK / 8; ++k8) {
                        const int ac = k8 * 8 + aq;
                        uint32_t af[2][4], bf[2][2];
                        #pragma unroll
                        for (int tm = 0; tm < 2; ++tm) {
                            const uint32_t* pp = cur + (wm * 32 + tm * 16 + ar) * LDA + ac;
                            af[tm][0] = pp[0];
                            af[tm][1] = pp[8 * LDA];
                            af[tm][2] = pp[4];
                            af[tm][3] = pp[8 * LDA + 4];
                        }
                        #pragma unroll
                        for (int tn = 0; tn < 2; ++tn) {
                            const uint32_t* q = W_s + (wn * 16 + tn * 8 + ar) * LDW
                                              + kt * BK + k8 * 8 + aq;
                            bf[tn][0] = q[0];
                            bf[tn][1] = q[4];
                        }
                        #pragma unroll
                        for (int tm = 0; tm < 2; ++tm)
                            #pragma unroll
                            for (int tn = 0; tn < 2; ++tn)
                                mma_tf32(&acc[tm][tn][0], af[tm], bf[tn]);
                    }
                }
            }

            // epilogue: sigmoid; i/o/f -> smem, z -> m (tf32-rounded) -> global
            #pragma unroll
            for (int tm = 0; tm < 2; ++tm) {
                #pragma unroll
                for (int tn = 0; tn < 2; ++tn) {
                    const int g = wn * 2 + tn;
                    #pragma unroll
                    for (int j = 0; j < 4; ++j) {
                        const int jb = j & 1, jh = j >> 1;
                        const int b  = wm * 32 + tm * 16 + ar + 8 * jh;
                        const int col = aq * 2 + jb;
                        const float pv = jb ? pre2[tm][jh][tn].y : pre2[tm][jh][tn].x;
                        const float s = fast_sigmoid(acc[tm][tn][j] + bhreg[tn][jb] + pv);
                        if (g == 2) {
                            const float mm = s * fast_tanh(c_s[b * UCOLS + col]);
                            g_m[b * H + uBase + col] = f2tf_f(mm);
                        } else {
                            const int slot = (g == 3) ? 2 : g;
                            iof_s[slot * (NB * UCOLS) + b * UCOLS + col] = s;
                        }
                    }
                }
            }
        }
        grid_barrier(bar_target); bar_target += NCTA;

        // ================= Phase 2: u + state update (zero-sync mainloop) ======
        {
            float2 preu2[2];
            #pragma unroll
            for (int jh = 0; jh < 2; ++jh) {
                const int b = warp * 16 + ar + 8 * jh;
                preu2[jh] = __ldcg(reinterpret_cast<const float2*>(
                    pre_t + (size_t)b * NPRE + 4 * H + uBase + aq * 2));
            }

            float acc2[4] = {};
            if (t > 0) {
                const float* m0 = g_m + (size_t)(warp * 16 + ar) * H;
                const float* m1 = m0 + 8 * H;
                const uint32_t* qbase = W_s + (32 + ar) * LDW;
                #pragma unroll 8
                for (int k8 = 0; k8 < K / 8; ++k8) {
                    const int c = k8 * 8 + aq;
                    uint32_t af[4], bf[2];
                    af[0] = __float_as_uint(__ldcg(m0 + c));
                    af[1] = __float_as_uint(__ldcg(m1 + c));
                    af[2] = __float_as_uint(__ldcg(m0 + c + 4));
                    af[3] = __float_as_uint(__ldcg(m1 + c + 4));
                    bf[0] = qbase[c];
                    bf[1] = qbase[c + 4];
                    mma_tf32(acc2, af, bf);
                }
            }

            #pragma unroll
            for (int j = 0; j < 4; ++j) {
                const int jb = j & 1, jh = j >> 1;
                const int b   = warp * 16 + ar + 8 * jh;
                const int col = aq * 2 + jb;
                const int n   = uBase + col;
                const float pv = jb ? preu2[jh].y : preu2[jh].x;
                const float bv = jb ? bureg.y : bureg.x;
                const float u  = fast_tanh(acc2[j] + bv + pv);
                const float ig = iof_s[0 * (NB * UCOLS) + b * UCOLS + col];
                const float og = iof_s[1 * (NB * UCOLS) + b * UCOLS + col];
                const float fg = iof_s[2 * (NB * UCOLS) + b * UCOLS + col];
                const float cn = ig * u + fg * c_s[b * UCOLS + col];
                c_s[b * UCOLS + col] = cn;
                const float hv = og * fast_tanh(cn);
                out[(size_t)t * NB * H + b * H + n] = hv;
                g_hr[b * H + n] = f2tf_f(hv);
                if (t == SEQ - 1) {
                    out[(size_t)SEQ * NB * H + b * H + n] = hv;               // h_n
                    out[(size_t)SEQ * NB * H + NB * H + b * H + n] = cn;      // c_n
                }
            }
        }
        grid_barrier(bar_target); bar_target += NCTA;
    }
}

extern "C" void kernel_launch(void* const* d_in, const int* in_sizes, int n_in,
                              void* d_out, int out_size) {
    (void)in_sizes; (void)n_in; (void)out_size;
    const float* X   = (const float*)d_in[0];
    const float* Wx  = (const float*)d_in[1];
    const float* bx  = (const float*)d_in[2];
    const float* Wh  = (const float*)d_in[3];
    const float* bh  = (const float*)d_in[4];
    const float* Wum = (const float*)d_in[5];
    const float* bum = (const float*)d_in[6];
    float* out = (float*)d_out;

    static_assert(SMEM_WORDS * 4 == 217728, "lstm smem layout");
    static_assert(P_SMEM * 4 == 110592, "pre smem layout");
    cudaFuncSetAttribute(lstm_kernel, cudaFuncAttributeMaxDynamicSharedMemorySize,
                         SMEM_WORDS * 4);
    cudaFuncSetAttribute(pre_kernel, cudaFuncAttributeMaxDynamicSharedMemorySize,
                         P_SMEM * 4);

    const size_t total4 = X4 + W4;
    round_kernel<<<(unsigned)((total4 + 255) / 256), 256>>>(
        (const float4*)X, (const float4*)Wx);
    pre_kernel<<<dim3(NPRE / 128, (SEQ * NB) / 128), 256, P_SMEM * 4>>>(bx);
    lstm_kernel<<<NCTA, 256, SMEM_WORDS * 4>>>(Wh, bh, Wum, bum, out);
}

// round 5
// speedup vs baseline: 1.5072x; 1.5072x over previous
#include <cuda_runtime.h>
#include <math.h>
#include <stdint.h>

// ---------------------------------------------------------------------------
// FPLSTM layer: S=512, B=128, I=H=1024
//   pre = X @ Wx^T + bx                         (cp.async 3-stage GEMM)
//   per step t (persistent kernel, 128 CTAs, weights SMEM-resident):
//     gates = sigmoid(pre[t,:,:4H] + h @ Wh^T + bh)   (i,o,z,f)
//     m = z * tanh(c)
//     u = tanh(pre[t,:,4H:] + m @ Wum^T + bum)
//     c = i*u + f*c ;  h = o*tanh(c)
// GEMM operands pre-rounded to tf32 (RNA) in global memory; all staging is raw
// cp.async (no register bounce, no conversions in hot loops). Recurrence
// phases use 2-buffer 1-tile-ahead cp.async pipelines.
// ---------------------------------------------------------------------------

namespace {
constexpr int SEQ  = 512;
constexpr int NB   = 128;
constexpr int K    = 1024;
constexpr int H    = 1024;
constexpr int NPRE = 5 * H;   // 5120

constexpr int NCTA  = 128;
constexpr int UCOLS = H / NCTA;       // 8 owned h-columns per CTA
constexpr int LDW   = K + 4;          // padded weight stride (words)
constexpr int BK    = 32;
constexpr int NKT   = K / BK;         // 32 K-tiles
constexpr int LDA   = BK + 4;         // 36 words (row=144B, 16B aligned)
constexpr int ABUF  = NB * LDA;       // 4608 words per A stage
// lstm dynamic smem layout (u32 words)
constexpr int OFF_W   = 0;                        // 40 rows x LDW
constexpr int OFF_AS  = 40 * LDW;                 // 41120
constexpr int OFF_IOF = OFF_AS + 2 * ABUF;        // 50336 : [3][128][8]
constexpr int OFF_C   = OFF_IOF + 3 * NB * UCOLS; // 53408 : [128][8]
constexpr int SMEM_WORDS = OFF_C + NB * UCOLS;    // 54432 -> 217728 bytes

// pre_kernel smem: 3 stages of (128 A rows + 128 B rows) x LDA
constexpr int P_STAGE = 256 * LDA;                // 9216 words
constexpr int P_SMEM  = 3 * P_STAGE;              // 27648 words -> 110592 bytes

constexpr size_t X4 = (size_t)SEQ * NB * K / 4;   // float4 count of X
constexpr size_t W4 = (size_t)NPRE * K / 4;       // float4 count of Wx
}

// Scratch (allocation-free __device__ globals)
__device__ __align__(16) float g_pre[(size_t)SEQ * NB * NPRE];
__device__ __align__(16) float g_xr[(size_t)SEQ * NB * K];   // tf32-rounded X
__device__ __align__(16) float g_wxr[(size_t)NPRE * K];      // tf32-rounded Wx
__device__ __align__(16) float g_hr[NB * H];                 // tf32-rounded h
__device__ __align__(16) float g_m[NB * H];                  // tf32-rounded m
__device__ unsigned g_bar;

__device__ __forceinline__ uint32_t f2tf(float f) {
    uint32_t u;
    asm("cvt.rna.tf32.f32 %0, %1;" : "=r"(u) : "f"(f));
    return u;
}
__device__ __forceinline__ float f2tf_f(float f) { return __uint_as_float(f2tf(f)); }

__device__ __forceinline__ void mma_tf32(float* c, const uint32_t* a, const uint32_t* b) {
    asm volatile(
        "mma.sync.aligned.m16n8k8.row.col.f32.tf32.tf32.f32 "
        "{%0,%1,%2,%3}, {%4,%5,%6,%7}, {%8,%9}, {%0,%1,%2,%3};\n"
        : "+f"(c[0]), "+f"(c[1]), "+f"(c[2]), "+f"(c[3])
        : "r"(a[0]), "r"(a[1]), "r"(a[2]), "r"(a[3]),
          "r"(b[0]), "r"(b[1]));
}

__device__ __forceinline__ float fast_sigmoid(float x) {
    return __fdividef(1.0f, 1.0f + __expf(-x));
}
__device__ __forceinline__ float fast_tanh(float x) {
    return 1.0f - __fdividef(2.0f, __expf(2.0f * x) + 1.0f);
}

__device__ __forceinline__ void cp16(uint32_t smem_byte_addr, const void* gptr) {
    asm volatile("cp.async.cg.shared.global [%0], [%1], 16;\n"
                 :: "r"(smem_byte_addr), "l"(gptr));
}
__device__ __forceinline__ void cp_commit() {
    asm volatile("cp.async.commit_group;\n");
}
template <int N>
__device__ __forceinline__ void cp_wait() {
    asm volatile("cp.async.wait_group %0;\n" :: "n"(N));
}

// ---------------------------------------------------------------------------
// round_kernel: tf32-round X and Wx into scratch; reset grid barrier
// ---------------------------------------------------------------------------
__global__ __launch_bounds__(256) void round_kernel(const float4* __restrict__ X,
                                                    const float4* __restrict__ Wx) {
    const size_t i = (size_t)blockIdx.x * 256 + threadIdx.x;
    if (i == 0) g_bar = 0u;
    if (i < X4) {
        const float4 v = X[i];
        float4 r = make_float4(f2tf_f(v.x), f2tf_f(v.y), f2tf_f(v.z), f2tf_f(v.w));
        reinterpret_cast<float4*>(g_xr)[i] = r;
    } else if (i < X4 + W4) {
        const size_t j = i - X4;
        const float4 v = Wx[j];
        float4 r = make_float4(f2tf_f(v.x), f2tf_f(v.y), f2tf_f(v.z), f2tf_f(v.w));
        reinterpret_cast<float4*>(g_wxr)[j] = r;
    }
}

// ---------------------------------------------------------------------------
// pre_kernel: pre = Xr @ Wxr^T + bx   (M=65536, N=5120, K=1024)
// BM=128, BN=128, BK=32, 256 threads, 3-stage cp.async pipeline.
// ---------------------------------------------------------------------------
__device__ __forceinline__ void pre_issue(uint32_t smbase, int stage,
                                          const float* __restrict__ Asrc,
                                          const float* __restrict__ Bsrc,
                                          int kt, int tid) {
    const uint32_t sb = smbase + (uint32_t)(stage * P_STAGE) * 4u;
    #pragma unroll
    for (int j = 0; j < 8; ++j) {
        const int i  = tid + j * 256;
        const int r  = i >> 3;
        const int ch = i & 7;
        const float* src = (r < 128)
            ? Asrc + (size_t)r * K + kt + ch * 4
            : Bsrc + (size_t)(r - 128) * K + kt + ch * 4;
        cp16(sb + (uint32_t)(r * LDA + ch * 4) * 4u, src);
    }
    cp_commit();
}

__global__ __launch_bounds__(256, 1) void pre_kernel(const float* __restrict__ bx) {
    extern __shared__ uint32_t sm_u[];
    const uint32_t smbase = (uint32_t)__cvta_generic_to_shared(sm_u);

    const int tid  = threadIdx.x;
    const int lane = tid & 31;
    const int warp = tid >> 5;
    const int wm = warp >> 2;        // 0..1  (64 rows each)
    const int wn = warp & 3;         // 0..3  (32 cols each)
    const int ar = lane >> 2;
    const int aq = lane & 3;

    const float* Asrc = g_xr  + (size_t)blockIdx.y * 128 * K;
    const float* Bsrc = g_wxr + (size_t)blockIdx.x * 128 * K;

    float acc[4][4][4] = {};

    pre_issue(smbase, 0, Asrc, Bsrc, 0, tid);
    pre_issue(smbase, 1, Asrc, Bsrc, BK, tid);

    #pragma unroll 1
    for (int kt = 0; kt < NKT; ++kt) {
        if (kt < NKT - 2) { cp_wait<1>(); } else { cp_wait<0>(); }
        __syncthreads();
        if (kt + 2 < NKT)
            pre_issue(smbase, (kt + 2) % 3, Asrc, Bsrc, (kt + 2) * BK, tid);

        const uint32_t* buf = sm_u + (kt % 3) * P_STAGE;
        #pragma unroll
        for (int k8 = 0; k8 < BK / 8; ++k8) {
            const int ac = k8 * 8 + aq;
            uint32_t af[4][4], bf[4][2];
            #pragma unroll
            for (int tm = 0; tm < 4; ++tm) {
                const uint32_t* p = buf + (wm * 64 + tm * 16 + ar) * LDA + ac;
                af[tm][0] = p[0];
                af[tm][1] = p[8 * LDA];
                af[tm][2] = p[4];
                af[tm][3] = p[8 * LDA + 4];
            }
            #pragma unroll
            for (int tn = 0; tn < 4; ++tn) {
                const uint32_t* q = buf + (128 + wn * 32 + tn * 8 + ar) * LDA + ac;
                bf[tn][0] = q[0];
                bf[tn][1] = q[4];
            }
            #pragma unroll
            for (int tm = 0; tm < 4; ++tm)
                #pragma unroll
                for (int tn = 0; tn < 4; ++tn)
                    mma_tf32(&acc[tm][tn][0], af[tm], bf[tn]);
        }
        __syncthreads();
    }

    #pragma unroll
    for (int tm = 0; tm < 4; ++tm) {
        #pragma unroll
        for (int tn = 0; tn < 4; ++tn) {
            const int r0 = wm * 64 + tm * 16 + ar;
            const int c0 = wn * 32 + tn * 8 + aq * 2;
            #pragma unroll
            for (int j = 0; j < 4; ++j) {
                const int rr = r0 + (j >> 1) * 8;
                const int cc = c0 + (j & 1);
                const int gm = blockIdx.y * 128 + rr;
                const int gn = blockIdx.x * 128 + cc;
                g_pre[(size_t)gm * NPRE + gn] = acc[tm][tn][j] + __ldg(bx + gn);
            }
        }
    }
}

// ---------------------------------------------------------------------------
// Persistent recurrence kernel
// ---------------------------------------------------------------------------
__device__ __forceinline__ void grid_barrier(unsigned target) {
    __syncthreads();
    if (threadIdx.x == 0) {
        asm volatile("red.release.gpu.global.add.u32 [%0], %1;\n"
                     :: "l"(&g_bar), "r"(1u) : "memory");
        unsigned v;
        do {
            asm volatile("ld.acquire.gpu.global.u32 %0, [%1];\n"
                         : "=r"(v) : "l"(&g_bar) : "memory");
        } while (v < target);
    }
    __syncthreads();
}

// copy one 128 x BK A-tile from global (tf32-rounded) into smem stage
__device__ __forceinline__ void lstm_issueA(uint32_t smbase, int stage,
                                            const float* __restrict__ src,
                                            int kt, int tid) {
    const uint32_t sb = smbase + (uint32_t)((OFF_AS + stage * ABUF)) * 4u;
    #pragma unroll
    for (int j = 0; j < 4; ++j) {
        const int i  = tid + j * 256;
        const int r  = i >> 3;
        const int ch = i & 7;
        cp16(sb + (uint32_t)(r * LDA + ch * 4) * 4u,
             src + (size_t)r * H + kt + ch * 4);
    }
    cp_commit();
}

__global__ __launch_bounds__(256, 1) void lstm_kernel(const float* __restrict__ Wh,
                                                      const float* __restrict__ bh,
                                                      const float* __restrict__ Wum,
                                                      const float* __restrict__ bum,
                                                      float* __restrict__ out) {
    extern __shared__ uint32_t sm_u[];
    const uint32_t smbase = (uint32_t)__cvta_generic_to_shared(sm_u);
    uint32_t* W_s   = sm_u + OFF_W;      // rows 0..31: Wh slices; 32..39: Wum slice
    float*    iof_s = reinterpret_cast<float*>(sm_u + OFF_IOF);  // [3][128][8]
    float*    c_s   = reinterpret_cast<float*>(sm_u + OFF_C);    // [128][8]

    const int tid   = threadIdx.x;
    const int lane  = tid & 31;
    const int warp  = tid >> 5;
    const int uBase = blockIdx.x * UCOLS;

    // ---- preload weight slices (fp32 -> tf32, once) ----
    for (int i = tid; i < 40 * 256; i += 256) {
        const int row = i >> 8;
        const int c4  = (i & 255) * 4;
        const float* src;
        if (row < 32) {
            const int g = row >> 3, r = row & 7;
            src = Wh + (size_t)(g * H + uBase + r) * K;
        } else {
            src = Wum + (size_t)(uBase + (row - 32)) * K;
        }
        const float4 v = *reinterpret_cast<const float4*>(src + c4);
        uint4 d = make_uint4(f2tf(v.x), f2tf(v.y), f2tf(v.z), f2tf(v.w));
        *reinterpret_cast<uint4*>(W_s + row * LDW + c4) = d;
    }
    for (int i = tid; i < NB * UCOLS; i += 256) c_s[i] = 0.0f;
    __syncthreads();

    // phase-1 warp layout: wm in [0,4) -> 32 batch rows; wn in [0,2) -> 16 gate cols
    const int wm = warp >> 1;
    const int wn = warp & 1;
    const int ar = lane >> 2;
    const int aq = lane & 3;

    float bhreg[2][2];
    #pragma unroll
    for (int tn = 0; tn < 2; ++tn)
        #pragma unroll
        for (int jb = 0; jb < 2; ++jb) {
            const int gi = wn * 16 + tn * 8 + aq * 2 + jb;
            bhreg[tn][jb] = bh[(gi >> 3) * H + uBase + (gi & 7)];
        }
    const float2 bureg = *reinterpret_cast<const float2*>(bum + uBase + aq * 2);

    unsigned bar_target = NCTA;

    for (int t = 0; t < SEQ; ++t) {
        const float* pre_t = g_pre + (size_t)t * NB * NPRE;

        // ================= Phase 1: gates =================
        {
            // prefetch pre slices for the epilogue
            float2 pre2[2][2][2];   // [tm][jh][tn]
            #pragma unroll
            for (int tm = 0; tm < 2; ++tm)
                #pragma unroll
                for (int jh = 0; jh < 2; ++jh)
                    #pragma unroll
                    for (int tn = 0; tn < 2; ++tn) {
                        const int b = wm * 32 + tm * 16 + ar + 8 * jh;
                        const int g = wn * 2 + tn;
                        pre2[tm][jh][tn] = __ldcg(reinterpret_cast<const float2*>(
                            pre_t + (size_t)b * NPRE + g * H + uBase + aq * 2));
                    }

            float acc[2][2][4] = {};
            if (t > 0) {
                lstm_issueA(smbase, 0, g_hr, 0, tid);
                lstm_issueA(smbase, 1, g_hr, BK, tid);
                #pragma unroll 1
                for (int kt = 0; kt < NKT; ++kt) {
                    if (kt < NKT - 1) { cp_wait<1>(); } else { cp_wait<0>(); }
                    __syncthreads();

                    const uint32_t* cur = sm_u + OFF_AS + (kt & 1) * ABUF;
                    #pragma unroll
                    for (int k8 = 0; k8 < BK / 8; ++k8) {
                        const int ac = k8 * 8 + aq;
                        uint32_t af[2][4], bf[2][2];
                        #pragma unroll
                        for (int tm = 0; tm < 2; ++tm) {
                            const uint32_t* pp = cur + (wm * 32 + tm * 16 + ar) * LDA + ac;
                            af[tm][0] = pp[0];
                            af[tm][1] = pp[8 * LDA];
                            af[tm][2] = pp[4];
                            af[tm][3] = pp[8 * LDA + 4];
                        }
                        #pragma unroll
                        for (int tn = 0; tn < 2; ++tn) {
                            const uint32_t* q = W_s + (wn * 16 + tn * 8 + ar) * LDW
                                              + kt * BK + k8 * 8 + aq;
                            bf[tn][0] = q[0];
                            bf[tn][1] = q[4];
                        }
                        #pragma unroll
                        for (int tm = 0; tm < 2; ++tm)
                            #pragma unroll
                            for (int tn = 0; tn < 2; ++tn)
                                mma_tf32(&acc[tm][tn][0], af[tm], bf[tn]);
                    }
                    __syncthreads();
                    if (kt + 2 < NKT)
                        lstm_issueA(smbase, kt & 1, g_hr, (kt + 2) * BK, tid);
                }
            }

            // epilogue: sigmoid; i/o/f -> smem, z -> m (tf32-rounded) -> global
            #pragma unroll
            for (int tm = 0; tm < 2; ++tm) {
                #pragma unroll
                for (int tn = 0; tn < 2; ++tn) {
                    const int g = wn * 2 + tn;
                    #pragma unroll
                    for (int j = 0; j < 4; ++j) {
                        const int jb = j & 1, jh = j >> 1;
                        const int b  = wm * 32 + tm * 16 + ar + 8 * jh;
                        const int col = aq * 2 + jb;
                        const float pv = jb ? pre2[tm][jh][tn].y : pre2[tm][jh][tn].x;
                        const float s = fast_sigmoid(acc[tm][tn][j] + bhreg[tn][jb] + pv);
                        if (g == 2) {
                            const float mm = s * fast_tanh(c_s[b * UCOLS + col]);
                            g_m[b * H + uBase + col] = f2tf_f(mm);
                        } else {
                            const int slot = (g == 3) ? 2 : g;
                            iof_s[slot * (NB * UCOLS) + b * UCOLS + col] = s;
                        }
                    }
                }
            }
        }
        grid_barrier(bar_target); bar_target += NCTA;

        // ================= Phase 2: u + state update =================
        {
            float2 preu2[2];
            #pragma unroll
            for (int jh = 0; jh < 2; ++jh) {
                const int b = warp * 16 + ar + 8 * jh;
                preu2[jh] = __ldcg(reinterpret_cast<const float2*>(
                    pre_t + (size_t)b * NPRE + 4 * H + uBase + aq * 2));
            }

            float acc2[4] = {};
            if (t > 0) {
                lstm_issueA(smbase, 0, g_m, 0, tid);
                lstm_issueA(smbase, 1, g_m, BK, tid);
                #pragma unroll 1
                for (int kt = 0; kt < NKT; ++kt) {
                    if (kt < NKT - 1) { cp_wait<1>(); } else { cp_wait<0>(); }
                    __syncthreads();

                    const uint32_t* cur = sm_u + OFF_AS + (kt & 1) * ABUF;
                    #pragma unroll
                    for (int k8 = 0; k8 < BK / 8; ++k8) {
                        const int ac = k8 * 8 + aq;
                        uint32_t af[4], bf[2];
                        const uint32_t* pp = cur + (warp * 16 + ar) * LDA + ac;
                        af[0] = pp[0];
                        af[1] = pp[8 * LDA];
                        af[2] = pp[4];
                        af[3] = pp[8 * LDA + 4];
                        const uint32_t* q = W_s + (32 + ar) * LDW + kt * BK + k8 * 8 + aq;
                        bf[0] = q[0];
                        bf[1] = q[4];
                        mma_tf32(acc2, af, bf);
                    }
                    __syncthreads();
                    if (kt + 2 < NKT)
                        lstm_issueA(smbase, kt & 1, g_m, (kt + 2) * BK, tid);
                }
            }

            #pragma unroll
            for (int j = 0; j < 4; ++j) {
                const int jb = j & 1, jh = j >> 1;
                const int b   = warp * 16 + ar + 8 * jh;
                const int col = aq * 2 + jb;
                const int n   = uBase + col;
                const float pv = jb ? preu2[jh].y : preu2[jh].x;
                const float bv = jb ? bureg.y : bureg.x;
                const float u  = fast_tanh(acc2[j] + bv + pv);
                const float ig = iof_s[0 * (NB * UCOLS) + b * UCOLS + col];
                const float og = iof_s[1 * (NB * UCOLS) + b * UCOLS + col];
                const float fg = iof_s[2 * (NB * UCOLS) + b * UCOLS + col];
                const float cn = ig * u + fg * c_s[b * UCOLS + col];
                c_s[b * UCOLS + col] = cn;
                const float hv = og * fast_tanh(cn);
                out[(size_t)t * NB * H + b * H + n] = hv;
                g_hr[b * H + n] = f2tf_f(hv);
                if (t == SEQ - 1) {
                    out[(size_t)SEQ * NB * H + b * H + n] = hv;               // h_n
                    out[(size_t)SEQ * NB * H + NB * H + b * H + n] = cn;      // c_n
                }
            }
        }
        grid_barrier(bar_target); bar_target += NCTA;
    }
}

extern "C" void kernel_launch(void* const* d_in, const int* in_sizes, int n_in,
                              void* d_out, int out_size) {
    (void)in_sizes; (void)n_in; (void)out_size;
    const float* X   = (const float*)d_in[0];
    const float* Wx  = (const float*)d_in[1];
    const float* bx  = (const float*)d_in[2];
    const float* Wh  = (const float*)d_in[3];
    const float* bh  = (const float*)d_in[4];
    const float* Wum = (const float*)d_in[5];
    const float* bum = (const float*)d_in[6];
    float* out = (float*)d_out;

    static_assert(SMEM_WORDS * 4 == 217728, "lstm smem layout");
    static_assert(P_SMEM * 4 == 110592, "pre smem layout");
    cudaFuncSetAttribute(lstm_kernel, cudaFuncAttributeMaxDynamicSharedMemorySize,
                         SMEM_WORDS * 4);
    cudaFuncSetAttribute(pre_kernel, cudaFuncAttributeMaxDynamicSharedMemorySize,
                         P_SMEM * 4);

    const size_t total4 = X4 + W4;
    round_kernel<<<(unsigned)((total4 + 255) / 256), 256>>>(
        (const float4*)X, (const float4*)Wx);
    pre_kernel<<<dim3(NPRE / 128, (SEQ * NB) / 128), 256, P_SMEM * 4>>>(bx);
    lstm_kernel<<<NCTA, 256, SMEM_WORDS * 4>>>(Wh, bh, Wum, bum, out);
}

// round 6
// speedup vs baseline: 3.0370x; 2.0149x over previous
#include <cuda_runtime.h>
#include <cuda_fp16.h>
#include <math.h>
#include <stdint.h>

// ---------------------------------------------------------------------------
// FPLSTM layer: S=512, B=128, I=H=1024
//   pre = X @ Wx^T + bx                         (cp.async 3-stage fp16 GEMM)
//   per step t (persistent kernel, 128 CTAs, fp16 weights SMEM-resident):
//     gates = sigmoid(pre[t,:,:4H] + h @ Wh^T + bh)   (i,o,z,f)
//     m = z * tanh(c)
//     u = tanh(pre[t,:,4H:] + m @ Wum^T + bum)
//     c = i*u + f*c ;  h = o*tanh(c)
// All GEMMs: mma.sync.m16n8k16 fp16 x fp16 -> fp32 accumulate. Operands
// pre-converted to fp16 once; staging is raw cp.async, 4-stage/3-ahead in the
// recurrence (covers L2 latency*BW), 3-stage in the pre GEMM.
// ---------------------------------------------------------------------------

namespace {
constexpr int SEQ  = 512;
constexpr int NB   = 128;
constexpr int K    = 1024;    // in elements (halves)
constexpr int H    = 1024;
constexpr int NPRE = 5 * H;   // 5120

constexpr int NCTA  = 128;
constexpr int UCOLS = H / NCTA;       // 8 owned h-columns per CTA
constexpr int LDWW  = K / 2 + 4;      // weight row stride in u32 words (516)
constexpr int BK    = 64;             // K-tile in halves (128 B rows)
constexpr int NKT   = K / BK;         // 16 tiles
constexpr int LDA   = 36;             // A row stride in words (32 data + 4 pad)
constexpr int ABUF  = NB * LDA;       // 4608 words per A stage
// lstm dynamic smem layout (u32 words)
constexpr int OFF_W   = 0;                        // 40 rows x LDWW
constexpr int OFF_AS  = 40 * LDWW;                // 20640
constexpr int OFF_IOF = OFF_AS + 4 * ABUF;        // 39072 : [3][128][8] f32
constexpr int OFF_C   = OFF_IOF + 3 * NB * UCOLS; // 42144 : [128][8] f32
constexpr int SMEM_WORDS = OFF_C + NB * UCOLS;    // 43168 -> 172672 bytes

// pre_kernel smem: 3 stages of (128 A rows + 128 B rows) x LDA words
constexpr int P_STAGE = 256 * LDA;                // 9216 words
constexpr int P_SMEM  = 3 * P_STAGE;              // 27648 words -> 110592 bytes
constexpr int NKT_P   = K / BK;                   // 16

constexpr size_t X4 = (size_t)SEQ * NB * K / 4;   // float4 count of X
constexpr size_t W4 = (size_t)NPRE * K / 4;       // float4 count of Wx
}

// Scratch (allocation-free __device__ globals)
__device__ __align__(16) float  g_pre[(size_t)SEQ * NB * NPRE];
__device__ __align__(16) __half g_xh[(size_t)SEQ * NB * K];   // fp16 X
__device__ __align__(16) __half g_wxh[(size_t)NPRE * K];      // fp16 Wx
__device__ __align__(16) __half g_hh[NB * H];                 // fp16 h state
__device__ __align__(16) __half g_mh[NB * H];                 // fp16 m
__device__ unsigned g_bar;

__device__ __forceinline__ void mma_f16(float* c, const uint32_t* a, const uint32_t* b) {
    asm volatile(
        "mma.sync.aligned.m16n8k16.row.col.f32.f16.f16.f32 "
        "{%0,%1,%2,%3}, {%4,%5,%6,%7}, {%8,%9}, {%0,%1,%2,%3};\n"
        : "+f"(c[0]), "+f"(c[1]), "+f"(c[2]), "+f"(c[3])
        : "r"(a[0]), "r"(a[1]), "r"(a[2]), "r"(a[3]),
          "r"(b[0]), "r"(b[1]));
}

__device__ __forceinline__ uint32_t pack_h2(float x, float y) {
    __half2 h = __floats2half2_rn(x, y);
    return *reinterpret_cast<uint32_t*>(&h);
}

__device__ __forceinline__ float fast_sigmoid(float x) {
    return __fdividef(1.0f, 1.0f + __expf(-x));
}
__device__ __forceinline__ float fast_tanh(float x) {
    return 1.0f - __fdividef(2.0f, __expf(2.0f * x) + 1.0f);
}

__device__ __forceinline__ void cp16(uint32_t smem_byte_addr, const void* gptr) {
    asm volatile("cp.async.cg.shared.global [%0], [%1], 16;\n"
                 :: "r"(smem_byte_addr), "l"(gptr));
}
__device__ __forceinline__ void cp_commit() {
    asm volatile("cp.async.commit_group;\n");
}
template <int N>
__device__ __forceinline__ void cp_wait() {
    asm volatile("cp.async.wait_group %0;\n" :: "n"(N));
}

// ---------------------------------------------------------------------------
// round_kernel: convert X and Wx to fp16 scratch; reset grid barrier
// ---------------------------------------------------------------------------
__global__ __launch_bounds__(256) void round_kernel(const float4* __restrict__ X,
                                                    const float4* __restrict__ Wx) {
    const size_t i = (size_t)blockIdx.x * 256 + threadIdx.x;
    if (i == 0) g_bar = 0u;
    if (i < X4) {
        const float4 v = X[i];
        uint2 d = make_uint2(pack_h2(v.x, v.y), pack_h2(v.z, v.w));
        reinterpret_cast<uint2*>(g_xh)[i] = d;
    } else if (i < X4 + W4) {
        const size_t j = i - X4;
        const float4 v = Wx[j];
        uint2 d = make_uint2(pack_h2(v.x, v.y), pack_h2(v.z, v.w));
        reinterpret_cast<uint2*>(g_wxh)[j] = d;
    }
}

// ---------------------------------------------------------------------------
// pre_kernel: pre = Xh @ Wxh^T + bx   (M=65536, N=5120, K=1024, fp16)
// BM=128, BN=128, BK=64 halves, 256 threads, 3-stage cp.async pipeline.
// ---------------------------------------------------------------------------
__device__ __forceinline__ void pre_issue(uint32_t smbase, int stage,
                                          const __half* __restrict__ Asrc,
                                          const __half* __restrict__ Bsrc,
                                          int kt, int tid) {
    const uint32_t sb = smbase + (uint32_t)(stage * P_STAGE) * 4u;
    #pragma unroll
    for (int j = 0; j < 8; ++j) {
        const int i  = tid + j * 256;
        const int r  = i >> 3;               // 0..255
        const int ch = i & 7;                // 8 x 16B per 128B row
        const __half* src = (r < 128)
            ? Asrc + (size_t)r * K + kt + ch * 8
            : Bsrc + (size_t)(r - 128) * K + kt + ch * 8;
        cp16(sb + (uint32_t)(r * LDA + ch * 4) * 4u, src);
    }
    cp_commit();
}

__global__ __launch_bounds__(256, 1) void pre_kernel(const float* __restrict__ bx) {
    extern __shared__ uint32_t sm_u[];
    const uint32_t smbase = (uint32_t)__cvta_generic_to_shared(sm_u);

    const int tid  = threadIdx.x;
    const int lane = tid & 31;
    const int warp = tid >> 5;
    const int wm = warp >> 2;        // 0..1  (64 rows each)
    const int wn = warp & 3;         // 0..3  (32 cols each)
    const int ar = lane >> 2;
    const int aq = lane & 3;

    const __half* Asrc = g_xh  + (size_t)blockIdx.y * 128 * K;
    const __half* Bsrc = g_wxh + (size_t)blockIdx.x * 128 * K;

    float acc[4][4][4] = {};

    pre_issue(smbase, 0, Asrc, Bsrc, 0, tid);
    pre_issue(smbase, 1, Asrc, Bsrc, BK, tid);

    #pragma unroll 1
    for (int kt = 0; kt < NKT_P; ++kt) {
        if (kt < NKT_P - 2) { cp_wait<1>(); } else { cp_wait<0>(); }
        __syncthreads();
        if (kt + 2 < NKT_P)
            pre_issue(smbase, (kt + 2) % 3, Asrc, Bsrc, (kt + 2) * BK, tid);

        const uint32_t* buf = sm_u + (kt % 3) * P_STAGE;
        #pragma unroll
        for (int g = 0; g < BK / 16; ++g) {          // 4 k16 groups
            const int ac = g * 8 + aq;
            uint32_t af[4][4], bf[4][2];
            #pragma unroll
            for (int tm = 0; tm < 4; ++tm) {
                const uint32_t* p = buf + (wm * 64 + tm * 16 + ar) * LDA + ac;
                af[tm][0] = p[0];
                af[tm][1] = p[8 * LDA];
                af[tm][2] = p[4];
                af[tm][3] = p[8 * LDA + 4];
            }
            #pragma unroll
            for (int tn = 0; tn < 4; ++tn) {
                const uint32_t* q = buf + (128 + wn * 32 + tn * 8 + ar) * LDA + ac;
                bf[tn][0] = q[0];
                bf[tn][1] = q[4];
            }
            #pragma unroll
            for (int tm = 0; tm < 4; ++tm)
                #pragma unroll
                for (int tn = 0; tn < 4; ++tn)
                    mma_f16(&acc[tm][tn][0], af[tm], bf[tn]);
        }
        __syncthreads();
    }

    #pragma unroll
    for (int tm = 0; tm < 4; ++tm) {
        #pragma unroll
        for (int tn = 0; tn < 4; ++tn) {
            const int r0 = wm * 64 + tm * 16 + ar;
            const int c0 = wn * 32 + tn * 8 + aq * 2;
            #pragma unroll
            for (int j = 0; j < 4; ++j) {
                const int rr = r0 + (j >> 1) * 8;
                const int cc = c0 + (j & 1);
                const int gm = blockIdx.y * 128 + rr;
                const int gn = blockIdx.x * 128 + cc;
                g_pre[(size_t)gm * NPRE + gn] = acc[tm][tn][j] + __ldg(bx + gn);
            }
        }
    }
}

// ---------------------------------------------------------------------------
// Persistent recurrence kernel
// ---------------------------------------------------------------------------
__device__ __forceinline__ void grid_barrier(unsigned target) {
    __syncthreads();
    if (threadIdx.x == 0) {
        asm volatile("red.release.gpu.global.add.u32 [%0], %1;\n"
                     :: "l"(&g_bar), "r"(1u) : "memory");
        unsigned v;
        do {
            asm volatile("ld.acquire.gpu.global.u32 %0, [%1];\n"
                         : "=r"(v) : "l"(&g_bar) : "memory");
        } while (v < target);
    }
    __syncthreads();
}

// copy one 128 x BK(halves) A-tile into smem stage (8 KB)
__device__ __forceinline__ void lstm_issueA(uint32_t smbase, int stage,
                                            const __half* __restrict__ src,
                                            int kt, int tid) {
    const uint32_t sb = smbase + (uint32_t)(OFF_AS + stage * ABUF) * 4u;
    #pragma unroll
    for (int j = 0; j < 4; ++j) {
        const int i  = tid + j * 256;
        const int r  = i >> 3;
        const int ch = i & 7;
        cp16(sb + (uint32_t)(r * LDA + ch * 4) * 4u,
             src + (size_t)r * H + kt + ch * 8);
    }
    cp_commit();
}

__global__ __launch_bounds__(256, 1) void lstm_kernel(const float* __restrict__ Wh,
                                                      const float* __restrict__ bh,
                                                      const float* __restrict__ Wum,
                                                      const float* __restrict__ bum,
                                                      float* __restrict__ out) {
    extern __shared__ uint32_t sm_u[];
    const uint32_t smbase = (uint32_t)__cvta_generic_to_shared(sm_u);
    uint32_t* W_s   = sm_u + OFF_W;      // rows 0..31: Wh slices; 32..39: Wum slice
    float*    iof_s = reinterpret_cast<float*>(sm_u + OFF_IOF);  // [3][128][8]
    float*    c_s   = reinterpret_cast<float*>(sm_u + OFF_C);    // [128][8]

    const int tid   = threadIdx.x;
    const int lane  = tid & 31;
    const int warp  = tid >> 5;
    const int uBase = blockIdx.x * UCOLS;

    // ---- preload weight slices (fp32 -> fp16x2 words, once) ----
    for (int i = tid; i < 40 * 512; i += 256) {
        const int row = i >> 9;          // 0..39
        const int w   = i & 511;         // word within row (2 halves)
        const float* src;
        if (row < 32) {
            const int g = row >> 3, r = row & 7;
            src = Wh + (size_t)(g * H + uBase + r) * K;
        } else {
            src = Wum + (size_t)(uBase + (row - 32)) * K;
        }
        const float2 v = *reinterpret_cast<const float2*>(src + w * 2);
        W_s[row * LDWW + w] = pack_h2(v.x, v.y);
    }
    for (int i = tid; i < NB * UCOLS; i += 256) c_s[i] = 0.0f;
    __syncthreads();

    // phase-1 warp layout: wm in [0,4) -> 32 batch rows; wn in [0,2) -> 16 gate cols
    const int wm = warp >> 1;
    const int wn = warp & 1;
    const int ar = lane >> 2;
    const int aq = lane & 3;

    float bhreg[2][2];
    #pragma unroll
    for (int tn = 0; tn < 2; ++tn)
        #pragma unroll
        for (int jb = 0; jb < 2; ++jb) {
            const int gi = wn * 16 + tn * 8 + aq * 2 + jb;
            bhreg[tn][jb] = bh[(gi >> 3) * H + uBase + (gi & 7)];
        }
    const float2 bureg = *reinterpret_cast<const float2*>(bum + uBase + aq * 2);

    unsigned bar_target = NCTA;

    for (int t = 0; t < SEQ; ++t) {
        const float* pre_t = g_pre + (size_t)t * NB * NPRE;

        // ================= Phase 1: gates =================
        {
            // prefetch pre slices for the epilogue
            float2 pre2[2][2][2];   // [tm][jh][tn]
            #pragma unroll
            for (int tm = 0; tm < 2; ++tm)
                #pragma unroll
                for (int jh = 0; jh < 2; ++jh)
                    #pragma unroll
                    for (int tn = 0; tn < 2; ++tn) {
                        const int b = wm * 32 + tm * 16 + ar + 8 * jh;
                        const int g = wn * 2 + tn;
                        pre2[tm][jh][tn] = __ldcg(reinterpret_cast<const float2*>(
                            pre_t + (size_t)b * NPRE + g * H + uBase + aq * 2));
                    }

            float acc[2][2][4] = {};
            if (t > 0) {
                lstm_issueA(smbase, 0, g_hh, 0 * BK, tid);
                lstm_issueA(smbase, 1, g_hh, 1 * BK, tid);
                lstm_issueA(smbase, 2, g_hh, 2 * BK, tid);
                #pragma unroll 1
                for (int kt = 0; kt < NKT; ++kt) {
                    if (kt < NKT - 3)      { cp_wait<2>(); }
                    else if (kt == NKT - 3){ cp_wait<2>(); }
                    else if (kt == NKT - 2){ cp_wait<1>(); }
                    else                   { cp_wait<0>(); }
                    __syncthreads();

                    const uint32_t* cur = sm_u + OFF_AS + (kt & 3) * ABUF;
                    #pragma unroll
                    for (int g = 0; g < BK / 16; ++g) {
                        const int ac = g * 8 + aq;
                        uint32_t af[2][4], bf[2][2];
                        #pragma unroll
                        for (int tm = 0; tm < 2; ++tm) {
                            const uint32_t* pp = cur + (wm * 32 + tm * 16 + ar) * LDA + ac;
                            af[tm][0] = pp[0];
                            af[tm][1] = pp[8 * LDA];
                            af[tm][2] = pp[4];
                            af[tm][3] = pp[8 * LDA + 4];
                        }
                        #pragma unroll
                        for (int tn = 0; tn < 2; ++tn) {
                            const uint32_t* q = W_s + (wn * 16 + tn * 8 + ar) * LDWW
                                              + kt * (BK / 2) + g * 8 + aq;
                            bf[tn][0] = q[0];
                            bf[tn][1] = q[4];
                        }
                        #pragma unroll
                        for (int tm = 0; tm < 2; ++tm)
                            #pragma unroll
                            for (int tn = 0; tn < 2; ++tn)
                                mma_f16(&acc[tm][tn][0], af[tm], bf[tn]);
                    }
                    if (kt + 3 < NKT)
                        lstm_issueA(smbase, (kt + 3) & 3, g_hh, (kt + 3) * BK, tid);
                }
            }

            // epilogue: sigmoid; i/o/f -> smem, z -> m (fp16) -> global
            #pragma unroll
            for (int tm = 0; tm < 2; ++tm) {
                #pragma unroll
                for (int tn = 0; tn < 2; ++tn) {
                    const int g = wn * 2 + tn;
                    #pragma unroll
                    for (int j = 0; j < 4; ++j) {
                        const int jb = j & 1, jh = j >> 1;
                        const int b  = wm * 32 + tm * 16 + ar + 8 * jh;
                        const int col = aq * 2 + jb;
                        const float pv = jb ? pre2[tm][jh][tn].y : pre2[tm][jh][tn].x;
                        const float s = fast_sigmoid(acc[tm][tn][j] + bhreg[tn][jb] + pv);
                        if (g == 2) {
                            const float mm = s * fast_tanh(c_s[b * UCOLS + col]);
                            g_mh[b * H + uBase + col] = __float2half_rn(mm);
                        } else {
                            const int slot = (g == 3) ? 2 : g;
                            iof_s[slot * (NB * UCOLS) + b * UCOLS + col] = s;
                        }
                    }
                }
            }
        }
        grid_barrier(bar_target); bar_target += NCTA;

        // ================= Phase 2: u + state update =================
        {
            float2 preu2[2];
            #pragma unroll
            for (int jh = 0; jh < 2; ++jh) {
                const int b = warp * 16 + ar + 8 * jh;
                preu2[jh] = __ldcg(reinterpret_cast<const float2*>(
                    pre_t + (size_t)b * NPRE + 4 * H + uBase + aq * 2));
            }

            float acc2[4] = {};
            if (t > 0) {
                lstm_issueA(smbase, 0, g_mh, 0 * BK, tid);
                lstm_issueA(smbase, 1, g_mh, 1 * BK, tid);
                lstm_issueA(smbase, 2, g_mh, 2 * BK, tid);
                #pragma unroll 1
                for (int kt = 0; kt < NKT; ++kt) {
                    if (kt < NKT - 2)      { cp_wait<2>(); }
                    else if (kt == NKT - 2){ cp_wait<1>(); }
                    else                   { cp_wait<0>(); }
                    __syncthreads();

                    const uint32_t* cur = sm_u + OFF_AS + (kt & 3) * ABUF;
                    #pragma unroll
                    for (int g = 0; g < BK / 16; ++g) {
                        const int ac = g * 8 + aq;
                        uint32_t af[4], bf[2];
                        const uint32_t* pp = cur + (warp * 16 + ar) * LDA + ac;
                        af[0] = pp[0];
                        af[1] = pp[8 * LDA];
                        af[2] = pp[4];
                        af[3] = pp[8 * LDA + 4];
                        const uint32_t* q = W_s + (32 + ar) * LDWW
                                          + kt * (BK / 2) + g * 8 + aq;
                        bf[0] = q[0];
                        bf[1] = q[4];
                        mma_f16(acc2, af, bf);
                    }
                    if (kt + 3 < NKT)
                        lstm_issueA(smbase, (kt + 3) & 3, g_mh, (kt + 3) * BK, tid);
                }
            }

            #pragma unroll
            for (int j = 0; j < 4; ++j) {
                const int jb = j & 1, jh = j >> 1;
                const int b   = warp * 16 + ar + 8 * jh;
                const int col = aq * 2 + jb;
                const int n   = uBase + col;
                const float pv = jb ? preu2[jh].y : preu2[jh].x;
                const float bv = jb ? bureg.y : bureg.x;
                const float u  = fast_tanh(acc2[j] + bv + pv);
                const float ig = iof_s[0 * (NB * UCOLS) + b * UCOLS + col];
                const float og = iof_s[1 * (NB * UCOLS) + b * UCOLS + col];
                const float fg = iof_s[2 * (NB * UCOLS) + b * UCOLS + col];
                const float cn = ig * u + fg * c_s[b * UCOLS + col];
                c_s[b * UCOLS + col] = cn;
                const float hv = og * fast_tanh(cn);
                out[(size_t)t * NB * H + b * H + n] = hv;
                g_hh[b * H + n] = __float2half_rn(hv);
                if (t == SEQ - 1) {
                    out[(size_t)SEQ * NB * H + b * H + n] = hv;               // h_n
                    out[(size_t)SEQ * NB * H + NB * H + b * H + n] = cn;      // c_n
                }
            }
        }
        grid_barrier(bar_target); bar_target += NCTA;
    }
}

extern "C" void kernel_launch(void* const* d_in, const int* in_sizes, int n_in,
                              void* d_out, int out_size) {
    (void)in_sizes; (void)n_in; (void)out_size;
    const float* X   = (const float*)d_in[0];
    const float* Wx  = (const float*)d_in[1];
    const float* bx  = (const float*)d_in[2];
    const float* Wh  = (const float*)d_in[3];
    const float* bh  = (const float*)d_in[4];
    const float* Wum = (const float*)d_in[5];
    const float* bum = (const float*)d_in[6];
    float* out = (float*)d_out;

    static_assert(SMEM_WORDS * 4 == 172672, "lstm smem layout");
    static_assert(P_SMEM * 4 == 110592, "pre smem layout");
    cudaFuncSetAttribute(lstm_kernel, cudaFuncAttributeMaxDynamicSharedMemorySize,
                         SMEM_WORDS * 4);
    cudaFuncSetAttribute(pre_kernel, cudaFuncAttributeMaxDynamicSharedMemorySize,
                         P_SMEM * 4);

    const size_t total4 = X4 + W4;
    round_kernel<<<(unsigned)((total4 + 255) / 256), 256>>>(
        (const float4*)X, (const float4*)Wx);
    pre_kernel<<<dim3(NPRE / 128, (SEQ * NB) / 128), 256, P_SMEM * 4>>>(bx);
    lstm_kernel<<<NCTA, 256, SMEM_WORDS * 4>>>(Wh, bh, Wum, bum, out);
}

// round 8
// speedup vs baseline: 3.1829x; 1.0481x over previous
#include <cuda_runtime.h>
#include <cuda_fp16.h>
#include <math.h>
#include <stdint.h>

// ---------------------------------------------------------------------------
// FPLSTM: S=512, B=128, I=H=1024.
//   pre = X @ Wx^T + bx            (SIMT fp16 mma, cp.async 3-stage)
//   recurrence: persistent, 128 CTAs in 2 INDEPENDENT groups of 64.
//   Group g owns batch rows [64g, 64g+64); CTA j in group owns 16 h-columns.
//   Weights (Wh 64 rows + Wum 16 rows, fp16) SMEM-resident; h/m tiles
//   (64 x 1024 fp16 = 128KB) streamed via 4-buffer/3-ahead cp.async.
//   Grid barriers are per-group (64 CTAs); groups drift freely.
// ---------------------------------------------------------------------------

namespace {
constexpr int SEQ  = 512;
constexpr int NB   = 128;
constexpr int K    = 1024;
constexpr int H    = 1024;
constexpr int NPRE = 5 * H;

constexpr int GCTA  = 64;            // CTAs per group
constexpr int GROWS = 64;            // batch rows per group
constexpr int UCOLS = 16;            // h-columns per CTA
constexpr int LDWW  = K / 2 + 4;     // weight row stride in u32 words (516)
constexpr int BK    = 64;            // K-tile in halves
constexpr int NKT   = K / BK;        // 16
constexpr int LDA   = 36;            // A row stride words (32 data + 4 pad)
constexpr int ABUF  = GROWS * LDA;   // 2304 words per stage (9216 B)
constexpr int IOFP  = 17;            // padded col stride for iof/c
constexpr int IOFSZ = GROWS * IOFP;  // 1088 words per gate slot

// lstm smem (u32 words)
constexpr int OFF_W   = 0;                      // 80 rows x LDWW
constexpr int OFF_AS  = 80 * LDWW;              // 41280
constexpr int OFF_IOF = OFF_AS + 4 * ABUF;      // 50496
constexpr int OFF_C   = OFF_IOF + 3 * IOFSZ;    // 53760
constexpr int SMEM_WORDS = OFF_C + IOFSZ;       // 54848 -> 219392 B

// pre_kernel (unchanged from round 6)
constexpr int LDA_P  = 36;
constexpr int P_STAGE = 256 * LDA_P;
constexpr int P_SMEM  = 3 * P_STAGE;
constexpr int BKP    = 64;
constexpr int NKT_P  = 16;
constexpr size_t X4 = (size_t)SEQ * NB * K / 4;
constexpr size_t W4 = (size_t)NPRE * K / 4;
}

__device__ __align__(16) float  g_pre[(size_t)SEQ * NB * NPRE];
__device__ __align__(16) __half g_xh[(size_t)SEQ * NB * K];
__device__ __align__(16) __half g_wxh[(size_t)NPRE * K];
__device__ __align__(16) __half g_hh[NB * H];
__device__ __align__(16) __half g_mh[NB * H];
__device__ unsigned g_bars[2];

__device__ __forceinline__ uint32_t pack_h2(float x, float y) {
    __half2 h = __floats2half2_rn(x, y);
    return *reinterpret_cast<uint32_t*>(&h);
}
__device__ __forceinline__ float fast_sigmoid(float x) {
    return __fdividef(1.0f, 1.0f + __expf(-x));
}
__device__ __forceinline__ float fast_tanh(float x) {
    return 1.0f - __fdividef(2.0f, __expf(2.0f * x) + 1.0f);
}
__device__ __forceinline__ void cp16(uint32_t saddr, const void* g) {
    asm volatile("cp.async.cg.shared.global [%0], [%1], 16;\n" :: "r"(saddr), "l"(g));
}
__device__ __forceinline__ void cp_commit() { asm volatile("cp.async.commit_group;\n"); }
template <int N> __device__ __forceinline__ void cp_wait() {
    asm volatile("cp.async.wait_group %0;\n" :: "n"(N));
}
__device__ __forceinline__ void mma_f16(float* c, const uint32_t* a, const uint32_t* b) {
    asm volatile(
        "mma.sync.aligned.m16n8k16.row.col.f32.f16.f16.f32 "
        "{%0,%1,%2,%3}, {%4,%5,%6,%7}, {%8,%9}, {%0,%1,%2,%3};\n"
        : "+f"(c[0]), "+f"(c[1]), "+f"(c[2]), "+f"(c[3])
        : "r"(a[0]), "r"(a[1]), "r"(a[2]), "r"(a[3]), "r"(b[0]), "r"(b[1]));
}

// ---------------------------------------------------------------------------
// round_kernel: fp16-convert X and Wx; reset group barriers
// ---------------------------------------------------------------------------
__global__ __launch_bounds__(256) void round_kernel(const float4* __restrict__ X,
                                                    const float4* __restrict__ Wx) {
    const size_t i = (size_t)blockIdx.x * 256 + threadIdx.x;
    if (i < 2) g_bars[i] = 0u;
    if (i < X4) {
        const float4 v = X[i];
        reinterpret_cast<uint2*>(g_xh)[i] = make_uint2(pack_h2(v.x, v.y), pack_h2(v.z, v.w));
    } else if (i < X4 + W4) {
        const size_t j = i - X4;
        const float4 v = Wx[j];
        reinterpret_cast<uint2*>(g_wxh)[j] = make_uint2(pack_h2(v.x, v.y), pack_h2(v.z, v.w));
    }
}

// ---------------------------------------------------------------------------
// pre_kernel: pre = Xh @ Wxh^T + bx (as round 6)
// ---------------------------------------------------------------------------
__device__ __forceinline__ void pre_issue(uint32_t smbase, int stage,
                                          const __half* __restrict__ Asrc,
                                          const __half* __restrict__ Bsrc,
                                          int kt, int tid) {
    const uint32_t sb = smbase + (uint32_t)(stage * P_STAGE) * 4u;
    #pragma unroll
    for (int j = 0; j < 8; ++j) {
        const int i  = tid + j * 256;
        const int r  = i >> 3;
        const int ch = i & 7;
        const __half* src = (r < 128)
            ? Asrc + (size_t)r * K + kt + ch * 8
            : Bsrc + (size_t)(r - 128) * K + kt + ch * 8;
        cp16(sb + (uint32_t)(r * LDA_P + ch * 4) * 4u, src);
    }
    cp_commit();
}

__global__ __launch_bounds__(256, 1) void pre_kernel(const float* __restrict__ bx) {
    extern __shared__ uint32_t sm_u[];
    const uint32_t smbase = (uint32_t)__cvta_generic_to_shared(sm_u);
    const int tid  = threadIdx.x;
    const int lane = tid & 31;
    const int warp = tid >> 5;
    const int wm = warp >> 2;
    const int wn = warp & 3;
    const int ar = lane >> 2;
    const int aq = lane & 3;

    const __half* Asrc = g_xh  + (size_t)blockIdx.y * 128 * K;
    const __half* Bsrc = g_wxh + (size_t)blockIdx.x * 128 * K;
    float acc[4][4][4] = {};

    pre_issue(smbase, 0, Asrc, Bsrc, 0, tid);
    pre_issue(smbase, 1, Asrc, Bsrc, BKP, tid);

    #pragma unroll 1
    for (int kt = 0; kt < NKT_P; ++kt) {
        if (kt < NKT_P - 2) { cp_wait<1>(); } else { cp_wait<0>(); }
        __syncthreads();
        if (kt + 2 < NKT_P)
            pre_issue(smbase, (kt + 2) % 3, Asrc, Bsrc, (kt + 2) * BKP, tid);

        const uint32_t* buf = sm_u + (kt % 3) * P_STAGE;
        #pragma unroll
        for (int gq = 0; gq < 4; ++gq) {
            const int ac = gq * 8 + aq;
            uint32_t af[4][4], bf[4][2];
            #pragma unroll
            for (int tm = 0; tm < 4; ++tm) {
                const uint32_t* p = buf + (wm * 64 + tm * 16 + ar) * LDA_P + ac;
                af[tm][0] = p[0];
                af[tm][1] = p[8 * LDA_P];
                af[tm][2] = p[4];
                af[tm][3] = p[8 * LDA_P + 4];
            }
            #pragma unroll
            for (int tn = 0; tn < 4; ++tn) {
                const uint32_t* q = buf + (128 + wn * 32 + tn * 8 + ar) * LDA_P + ac;
                bf[tn][0] = q[0];
                bf[tn][1] = q[4];
            }
            #pragma unroll
            for (int tm = 0; tm < 4; ++tm)
                #pragma unroll
                for (int tn = 0; tn < 4; ++tn)
                    mma_f16(&acc[tm][tn][0], af[tm], bf[tn]);
        }
        __syncthreads();
    }

    #pragma unroll
    for (int tm = 0; tm < 4; ++tm)
        #pragma unroll
        for (int tn = 0; tn < 4; ++tn) {
            const int r0 = wm * 64 + tm * 16 + ar;
            const int c0 = wn * 32 + tn * 8 + aq * 2;
            #pragma unroll
            for (int j = 0; j < 4; ++j) {
                const int rr = r0 + (j >> 1) * 8;
                const int cc = c0 + (j & 1);
                const int gm = blockIdx.y * 128 + rr;
                const int gn = blockIdx.x * 128 + cc;
                g_pre[(size_t)gm * NPRE + gn] = acc[tm][tn][j] + __ldg(bx + gn);
            }
        }
}

// ---------------------------------------------------------------------------
// Persistent recurrence kernel, 2 independent groups of 64 CTAs
// ---------------------------------------------------------------------------
__device__ __forceinline__ void group_barrier(unsigned* bar, unsigned target) {
    __syncthreads();
    if (threadIdx.x == 0) {
        asm volatile("red.release.gpu.global.add.u32 [%0], %1;\n"
                     :: "l"(bar), "r"(1u) : "memory");
        unsigned v;
        do {
            asm volatile("ld.acquire.gpu.global.u32 %0, [%1];\n"
                         : "=r"(v) : "l"(bar) : "memory");
        } while (v < target);
    }
    __syncthreads();
}

// copy one 64 x 64-half A-tile (8KB) into smem stage
__device__ __forceinline__ void lstm_issueA(uint32_t smbase, int stage,
                                            const __half* __restrict__ src,
                                            int kt, int tid) {
    const uint32_t sb = smbase + (uint32_t)(OFF_AS + stage * ABUF) * 4u;
    #pragma unroll
    for (int q = 0; q < 2; ++q) {
        const int i  = tid + q * 256;
        const int r  = i >> 3;
        const int ch = i & 7;
        cp16(sb + (uint32_t)(r * LDA + ch * 4) * 4u,
             src + (size_t)r * H + kt + ch * 8);
    }
    cp_commit();
}

__global__ __launch_bounds__(256, 1) void lstm_kernel(const float* __restrict__ Wh,
                                                      const float* __restrict__ bh,
                                                      const float* __restrict__ Wum,
                                                      const float* __restrict__ bum,
                                                      float* __restrict__ out) {
    extern __shared__ uint32_t sm_u[];
    const uint32_t smbase = (uint32_t)__cvta_generic_to_shared(sm_u);
    uint32_t* W_s  = sm_u + OFF_W;
    float*    iof  = reinterpret_cast<float*>(sm_u + OFF_IOF);
    float*    c_s  = reinterpret_cast<float*>(sm_u + OFF_C);

    const int tid   = threadIdx.x;
    const int lane  = tid & 31;
    const int warp  = tid >> 5;
    const int cta   = blockIdx.x;
    const int grp   = cta >> 6;
    const int jj    = cta & 63;
    const int uBase = jj * UCOLS;
    const int gRow0 = grp * GROWS;
    unsigned* bar   = &g_bars[grp];

    // ---- weight preload: rows 0..63 = Wh[(n>>4)*H + uBase + (n&15)],
    //      rows 64..79 = Wum[uBase + r] ; fp32 -> fp16x2 words ----
    for (int i = tid; i < 80 * 512; i += 256) {
        const int row = i >> 9;
        const int w   = i & 511;
        const float* src = (row < 64)
            ? Wh  + (size_t)((row >> 4) * H + uBase + (row & 15)) * K
            : Wum + (size_t)(uBase + (row - 64)) * K;
        const float2 v = *reinterpret_cast<const float2*>(src + w * 2);
        W_s[row * LDWW + w] = pack_h2(v.x, v.y);
    }
    for (int i = tid; i < IOFSZ; i += 256) c_s[i] = 0.0f;
    __syncthreads();

    const int ar = lane >> 2;
    const int aq = lane & 3;
    // phase-1 warp layout: wm1 (0..3) -> 16 batch rows, wn1 (0..1) -> 32 gate cols
    const int wm1 = warp >> 1;
    const int wn1 = warp & 1;

    float bhreg[4][2];
    #pragma unroll
    for (int tn = 0; tn < 4; ++tn)
        #pragma unroll
        for (int jb = 0; jb < 2; ++jb) {
            const int n = wn1 * 32 + tn * 8 + aq * 2 + jb;
            bhreg[tn][jb] = bh[(n >> 4) * H + uBase + (n & 15)];
        }
    float bureg[2][2];
    #pragma unroll
    for (int tn = 0; tn < 2; ++tn)
        #pragma unroll
        for (int jb = 0; jb < 2; ++jb)
            bureg[tn][jb] = bum[uBase + tn * 8 + aq * 2 + jb];

    unsigned tgt = GCTA;

    #pragma unroll 1
    for (int t = 0; t < SEQ; ++t) {
        const float* pre_t = g_pre + (size_t)t * NB * NPRE;

        // ================= Phase 1: gates =================
        {
            float2 pre2[4][2];
            #pragma unroll
            for (int tn = 0; tn < 4; ++tn)
                #pragma unroll
                for (int jh = 0; jh < 2; ++jh) {
                    const int b  = wm1 * 16 + ar + 8 * jh;
                    const int n0 = wn1 * 32 + tn * 8 + aq * 2;
                    pre2[tn][jh] = __ldcg(reinterpret_cast<const float2*>(
                        pre_t + (size_t)(gRow0 + b) * NPRE + (n0 >> 4) * H + uBase + (n0 & 15)));
                }

            float acc[4][4] = {};
            if (t > 0) {
                const __half* hsrc = g_hh + (size_t)gRow0 * H;
                lstm_issueA(smbase, 0, hsrc, 0, tid);
                lstm_issueA(smbase, 1, hsrc, 64, tid);
                lstm_issueA(smbase, 2, hsrc, 128, tid);
                #pragma unroll 1
                for (int kt = 0; kt < NKT; ++kt) {
                    if (kt < NKT - 2)      { cp_wait<2>(); }
                    else if (kt == NKT - 2){ cp_wait<1>(); }
                    else                   { cp_wait<0>(); }
                    __syncthreads();
                    if (kt + 3 < NKT)
                        lstm_issueA(smbase, (kt + 3) & 3, hsrc, (kt + 3) * BK, tid);

                    const uint32_t* cur = sm_u + OFF_AS + (kt & 3) * ABUF;
                    #pragma unroll
                    for (int g4 = 0; g4 < 4; ++g4) {
                        const int ac = g4 * 8 + aq;
                        uint32_t af[4];
                        const uint32_t* p = cur + (wm1 * 16 + ar) * LDA + ac;
                        af[0] = p[0];
                        af[1] = p[8 * LDA];
                        af[2] = p[4];
                        af[3] = p[8 * LDA + 4];
                        #pragma unroll
                        for (int tn = 0; tn < 4; ++tn) {
                            uint32_t bf[2];
                            const uint32_t* q = W_s + (wn1 * 32 + tn * 8 + ar) * LDWW
                                              + kt * 32 + g4 * 8 + aq;
                            bf[0] = q[0];
                            bf[1] = q[4];
                            mma_f16(&acc[tn][0], af, bf);
                        }
                    }
                }
            }

            // epilogue: sigmoid; i/o/f -> smem, z -> m (fp16) -> global
            #pragma unroll
            for (int tn = 0; tn < 4; ++tn) {
                const int n0   = wn1 * 32 + tn * 8 + aq * 2;
                const int gate = n0 >> 4;
                const int col0 = n0 & 15;
                #pragma unroll
                for (int jh = 0; jh < 2; ++jh) {
                    const int b = wm1 * 16 + ar + 8 * jh;
                    const float s0 = fast_sigmoid(acc[tn][2 * jh + 0] + bhreg[tn][0] + pre2[tn][jh].x);
                    const float s1 = fast_sigmoid(acc[tn][2 * jh + 1] + bhreg[tn][1] + pre2[tn][jh].y);
                    if (gate == 2) {
                        const float m0 = s0 * fast_tanh(c_s[b * IOFP + col0]);
                        const float m1 = s1 * fast_tanh(c_s[b * IOFP + col0 + 1]);
                        *reinterpret_cast<uint32_t*>(
                            g_mh + (size_t)(gRow0 + b) * H + uBase + col0) = pack_h2(m0, m1);
                    } else {
                        const int slot = (gate == 3) ? 2 : gate;
                        iof[slot * IOFSZ + b * IOFP + col0]     = s0;
                        iof[slot * IOFSZ + b * IOFP + col0 + 1] = s1;
                    }
                }
            }
        }
        group_barrier(bar, tgt); tgt += GCTA;

        // ================= Phase 2: u + state update =================
        {
            float2 preu[2][2];
            if (warp < 4) {
                #pragma unroll
                for (int tn = 0; tn < 2; ++tn)
                    #pragma unroll
                    for (int jh = 0; jh < 2; ++jh) {
                        const int b = warp * 16 + ar + 8 * jh;
                        preu[tn][jh] = __ldcg(reinterpret_cast<const float2*>(
                            pre_t + (size_t)(gRow0 + b) * NPRE + 4 * H + uBase + tn * 8 + aq * 2));
                    }
            }

            float acc2[2][4] = {};
            if (t > 0) {
                const __half* msrc = g_mh + (size_t)gRow0 * H;
                lstm_issueA(smbase, 0, msrc, 0, tid);
                lstm_issueA(smbase, 1, msrc, 64, tid);
                lstm_issueA(smbase, 2, msrc, 128, tid);
                #pragma unroll 1
                for (int kt = 0; kt < NKT; ++kt) {
                    if (kt < NKT - 2)      { cp_wait<2>(); }
                    else if (kt == NKT - 2){ cp_wait<1>(); }
                    else                   { cp_wait<0>(); }
                    __syncthreads();
                    if (kt + 3 < NKT)
                        lstm_issueA(smbase, (kt + 3) & 3, msrc, (kt + 3) * BK, tid);

                    if (warp < 4) {
                        const uint32_t* cur = sm_u + OFF_AS + (kt & 3) * ABUF;
                        #pragma unroll
                        for (int g4 = 0; g4 < 4; ++g4) {
                            const int ac = g4 * 8 + aq;
                            uint32_t af[4];
                            const uint32_t* p = cur + (warp * 16 + ar) * LDA + ac;
                            af[0] = p[0];
                            af[1] = p[8 * LDA];
                            af[2] = p[4];
                            af[3] = p[8 * LDA + 4];
                            #pragma unroll
                            for (int tn = 0; tn < 2; ++tn) {
                                uint32_t bf[2];
                                const uint32_t* q = W_s + (64 + tn * 8 + ar) * LDWW
                                                  + kt * 32 + g4 * 8 + aq;
                                bf[0] = q[0];
                                bf[1] = q[4];
                                mma_f16(&acc2[tn][0], af, bf);
                            }
                        }
                    }
                }
            }

            if (warp < 4) {
                #pragma unroll
                for (int tn = 0; tn < 2; ++tn) {
                    const int col0 = tn * 8 + aq * 2;
                    #pragma unroll
                    for (int jh = 0; jh < 2; ++jh) {
                        const int b = warp * 16 + ar + 8 * jh;
                        const float u0 = fast_tanh(acc2[tn][2 * jh + 0] + bureg[tn][0] + preu[tn][jh].x);
                        const float u1 = fast_tanh(acc2[tn][2 * jh + 1] + bureg[tn][1] + preu[tn][jh].y);
                        const float ig0 = iof[0 * IOFSZ + b * IOFP + col0];
                        const float ig1 = iof[0 * IOFSZ + b * IOFP + col0 + 1];
                        const float og0 = iof[1 * IOFSZ + b * IOFP + col0];
                        const float og1 = iof[1 * IOFSZ + b * IOFP + col0 + 1];
                        const float fg0 = iof[2 * IOFSZ + b * IOFP + col0];
                        const float fg1 = iof[2 * IOFSZ + b * IOFP + col0 + 1];
                        const float cn0 = ig0 * u0 + fg0 * c_s[b * IOFP + col0];
                        const float cn1 = ig1 * u1 + fg1 * c_s[b * IOFP + col0 + 1];
                        c_s[b * IOFP + col0]     = cn0;
                        c_s[b * IOFP + col0 + 1] = cn1;
                        const float hv0 = og0 * fast_tanh(cn0);
                        const float hv1 = og1 * fast_tanh(cn1);
                        *reinterpret_cast<float2*>(
                            out + ((size_t)t * NB + gRow0 + b) * H + uBase + col0) =
                            make_float2(hv0, hv1);
                        *reinterpret_cast<uint32_t*>(
                            g_hh + (size_t)(gRow0 + b) * H + uBase + col0) = pack_h2(hv0, hv1);
                        if (t == SEQ - 1) {
                            float* hn = out + ((size_t)SEQ * NB + gRow0 + b) * H + uBase + col0;
                            float* cn = hn + (size_t)NB * H;
                            *reinterpret_cast<float2*>(hn) = make_float2(hv0, hv1);
                            *reinterpret_cast<float2*>(cn) = make_float2(cn0, cn1);
                        }
                    }
                }
            }
        }
        group_barrier(bar, tgt); tgt += GCTA;
    }
}

extern "C" void kernel_launch(void* const* d_in, const int* in_sizes, int n_in,
                              void* d_out, int out_size) {
    (void)in_sizes; (void)n_in; (void)out_size;
    const float* X   = (const float*)d_in[0];
    const float* Wx  = (const float*)d_in[1];
    const float* bx  = (const float*)d_in[2];
    const float* Wh  = (const float*)d_in[3];
    const float* bh  = (const float*)d_in[4];
    const float* Wum = (const float*)d_in[5];
    const float* bum = (const float*)d_in[6];
    float* out = (float*)d_out;

    static_assert(SMEM_WORDS * 4 == 219392, "lstm smem layout");
    cudaFuncSetAttribute(lstm_kernel, cudaFuncAttributeMaxDynamicSharedMemorySize,
                         SMEM_WORDS * 4);
    cudaFuncSetAttribute(pre_kernel, cudaFuncAttributeMaxDynamicSharedMemorySize,
                         P_SMEM * 4);

    const size_t total4 = X4 + W4;
    round_kernel<<<(unsigned)((total4 + 255) / 256), 256>>>(
        (const float4*)X, (const float4*)Wx);
    pre_kernel<<<dim3(NPRE / 128, (SEQ * NB) / 128), 256, P_SMEM * 4>>>(bx);
    lstm_kernel<<<128, 256, SMEM_WORDS * 4>>>(Wh, bh, Wum, bum, out);
}